// round 7
// baseline (speedup 1.0000x reference)
#include <cuda_runtime.h>

// GRU sequence encoder, round 7.
// N=16384, L=512, ES=32, HS=64, gates [r|z|n] (torch order).
//
// P[v][g] = emb[v].w_ih[g] + b_ih[g] precomputed (32000x192, L2-resident).
// Counting sort by length (desc), 16 seqs per CTA group.
// 192-thread CTAs, two 96-thread halves: half H handles seqs [8H, 8H+8).
// Within a half, thread jj owns gate rows (2jj, 2jj+1): each broadcast
// h LDS.128 feeds 4 FFMA2. 12 warps/SM for latency hiding.

#define N_SEQ   16384
#define L_SEQ   512
#define ES_DIM  32
#define HS_DIM  64
#define G3      192
#define WG      16
#define WGH     8              // seqs per half
#define NGROUP  (N_SEQ / WG)   // 1024
#define NBUCKET 513
#define VOCAB   32000
#define NT      192

__device__ float P[VOCAB * G3];
__device__ int d_len[N_SEQ];
__device__ int d_bucket[NBUCKET];
__device__ int d_off[NBUCKET];
__device__ int d_sorted[N_SEQ];
__device__ int g_ctr;

#define FFMA2(acc, a, b) \
    asm("fma.rn.f32x2 %0, %1, %2, %0;" : "+l"(acc) : "l"(a), "l"(b))

__device__ __forceinline__ float pairsum(unsigned long long v) {
    return __uint_as_float((unsigned)v) + __uint_as_float((unsigned)(v >> 32));
}

// ---------------- prepass ----------------

__global__ void zero_kernel() {
    int t = threadIdx.x;
    if (t < NBUCKET) d_bucket[t] = 0;
    if (t == NBUCKET) g_ctr = 0;
}

#define LEN_CTAS 2048
#define P_ROWS_PER_CTA 64

__global__ void len_pre_kernel(const int* __restrict__ x,
                               const float* __restrict__ emb,
                               const float* __restrict__ w_ih,
                               const float* __restrict__ b_ih)
{
    if (blockIdx.x < LEN_CTAS) {
        int seq  = blockIdx.x * 8 + (threadIdx.x >> 5);
        int lane = threadIdx.x & 31;
        const int4* row = reinterpret_cast<const int4*>(x + (long)seq * L_SEQ);
        int c = 0;
        #pragma unroll
        for (int k = 0; k < 4; k++) {
            int4 v = row[lane + 32 * k];
            c += (v.x != 0) + (v.y != 0) + (v.z != 0) + (v.w != 0);
        }
        #pragma unroll
        for (int off = 16; off > 0; off >>= 1) c += __shfl_xor_sync(~0u, c, off);
        if (lane == 0) {
            d_len[seq] = c;
            atomicAdd(&d_bucket[c], 1);
        }
    } else {
        int j = threadIdx.x;
        if (j >= G3) return;
        float w[ES_DIM];
        {
            const float4* wr = reinterpret_cast<const float4*>(w_ih + (long)j * ES_DIM);
            #pragma unroll
            for (int k = 0; k < ES_DIM / 4; k++) {
                float4 v = wr[k];
                w[4*k+0] = v.x; w[4*k+1] = v.y; w[4*k+2] = v.z; w[4*k+3] = v.w;
            }
        }
        const float bj = b_ih[j];
        int v0 = (blockIdx.x - LEN_CTAS) * P_ROWS_PER_CTA;
        for (int v = v0; v < v0 + P_ROWS_PER_CTA && v < VOCAB; v++) {
            const float4* er = reinterpret_cast<const float4*>(emb + (long)v * ES_DIM);
            float acc = bj;
            #pragma unroll
            for (int k = 0; k < ES_DIM / 4; k++) {
                float4 e = __ldg(&er[k]);
                acc = fmaf(w[4*k+0], e.x, acc);
                acc = fmaf(w[4*k+1], e.y, acc);
                acc = fmaf(w[4*k+2], e.z, acc);
                acc = fmaf(w[4*k+3], e.w, acc);
            }
            P[(long)v * G3 + j] = acc;
        }
    }
}

__global__ void scan_scatter_kernel() {
    __shared__ int sb[NBUCKET], so[NBUCKET];
    int t = threadIdx.x;
    for (int i = t; i < NBUCKET; i += blockDim.x) sb[i] = d_bucket[i];
    __syncthreads();
    if (t == 0) {
        int run = 0;
        for (int l = NBUCKET - 1; l >= 0; l--) { so[l] = run; run += sb[l]; }
    }
    __syncthreads();
    for (int i = t; i < NBUCKET; i += blockDim.x) d_off[i] = so[i];
    __syncthreads();
    for (int seq = t; seq < N_SEQ; seq += blockDim.x) {
        int l = d_len[seq];
        int pos = atomicAdd(&d_off[l], 1);
        d_sorted[pos] = seq;
    }
}

// ---------------- main ----------------

__launch_bounds__(NT, 2)
__global__ void gru_main(const int*   __restrict__ x,
                         const float* __restrict__ w_hh,
                         const float* __restrict__ b_hh,
                         float*       __restrict__ out)
{
    __shared__ float  gx[2][WG][G3];        // 24 KB (dbl-buffered P rows)
    __shared__ float  gate[3][WG][HS_DIM];  // 12 KB
    __shared__ float4 h4[WG][HS_DIM / 4];   //  4 KB
    __shared__ int    seq_sm[WG], len_sm[WG], gid_sm;

    const int j  = threadIdx.x;
    const int jj = j % 96;                  // row-pair owner within half
    const int sh = j / 96;                  // half: 0 -> seqs 0..7, 1 -> 8..15
    const int s0 = sh * WGH;
    const int r0 = 2 * jj;                  // gate rows r0, r0+1
    const int gsel = r0 >> 6;
    const int i2 = r0 & 63;

    // two recurrent weight rows in registers (64-bit packed pairs)
    ulonglong2 w0[HS_DIM / 4], w1[HS_DIM / 4];
    {
        const ulonglong2* wp0 = reinterpret_cast<const ulonglong2*>(w_hh + (long)r0 * HS_DIM);
        const ulonglong2* wp1 = reinterpret_cast<const ulonglong2*>(w_hh + (long)(r0 + 1) * HS_DIM);
        #pragma unroll
        for (int k = 0; k < HS_DIM / 4; k++) { w0[k] = wp0[k]; w1[k] = wp1[k]; }
    }
    const float bh0 = b_hh[r0];
    const float bh1 = b_hh[r0 + 1];

    while (true) {
        if (j == 0) gid_sm = atomicAdd(&g_ctr, 1);
        __syncthreads();
        const int g = gid_sm;
        if (g >= NGROUP) break;

        if (j < WG) {
            int s = d_sorted[g * WG + j];
            seq_sm[j] = s;
            len_sm[j] = d_len[s];
        }
        for (int u = j; u < WG * (HS_DIM / 4); u += NT) {
            reinterpret_cast<float4*>(h4)[u] = make_float4(0.f, 0.f, 0.f, 0.f);
        }
        __syncthreads();

        const int maxlen = len_sm[0];
        int xoff[WGH];
        #pragma unroll
        for (int q = 0; q < WGH; q++) xoff[q] = seq_sm[s0 + q] * L_SEQ;

        if (maxlen > 0) {
            // prologue: gather gx(0) for own half (float2 per thread per seq)
            #pragma unroll
            for (int q = 0; q < WGH; q++) {
                int tok = __ldg(&x[xoff[q]]);
                *reinterpret_cast<float2*>(&gx[0][s0 + q][r0]) =
                    __ldg(reinterpret_cast<const float2*>(&P[(long)tok * G3 + r0]));
            }
            __syncthreads();

            int p = 0;
            for (int t = 0; t < maxlen; t++) {
                const int tn = (t + 1 < L_SEQ) ? t + 1 : L_SEQ - 1;

                // matvec over own half + prefetch gx(t+1) into idle buffer
                #pragma unroll
                for (int q = 0; q < WGH; q++) {
                    const int s = s0 + q;
                    int tok = __ldg(&x[xoff[q] + tn]);
                    float2 pre = __ldg(reinterpret_cast<const float2*>(
                                           &P[(long)tok * G3 + r0]));

                    unsigned long long a0 = 0ull, a1 = 0ull;
                    const ulonglong2* hp = reinterpret_cast<const ulonglong2*>(&h4[s][0]);
                    #pragma unroll
                    for (int k = 0; k < HS_DIM / 4; k++) {
                        ulonglong2 hv = hp[k];
                        FFMA2(a0, w0[k].x, hv.x);
                        FFMA2(a0, w0[k].y, hv.y);
                        FFMA2(a1, w1[k].x, hv.x);
                        FFMA2(a1, w1[k].y, hv.y);
                    }
                    *reinterpret_cast<float2*>(&gate[gsel][s][i2]) =
                        make_float2(pairsum(a0) + bh0, pairsum(a1) + bh1);
                    *reinterpret_cast<float2*>(&gx[1 - p][s][r0]) = pre;
                }
                __syncthreads();   // gates + gx(t+1) ready; h reads done

                // update: 512 element-pairs over 192 threads
                #pragma unroll
                for (int q = 0; q < (WG * HS_DIM / 2 + NT - 1) / NT; q++) {
                    int u = j + NT * q;
                    if (u < WG * HS_DIM / 2) {
                        int s = u >> 5, ii = (u & 31) * 2;
                        float2 gxr = *reinterpret_cast<const float2*>(&gx[p][s][ii]);
                        float2 gxz = *reinterpret_cast<const float2*>(&gx[p][s][64 + ii]);
                        float2 gxn = *reinterpret_cast<const float2*>(&gx[p][s][128 + ii]);
                        float2 ghr = *reinterpret_cast<const float2*>(&gate[0][s][ii]);
                        float2 ghz = *reinterpret_cast<const float2*>(&gate[1][s][ii]);
                        float2 ghn = *reinterpret_cast<const float2*>(&gate[2][s][ii]);
                        float* hp = reinterpret_cast<float*>(h4[s]) + ii;
                        float2 ho = *reinterpret_cast<const float2*>(hp);
                        bool live = (t < len_sm[s]);

                        float rx = __fdividef(1.0f, 1.0f + __expf(-(gxr.x + ghr.x)));
                        float ry = __fdividef(1.0f, 1.0f + __expf(-(gxr.y + ghr.y)));
                        float zx = __fdividef(1.0f, 1.0f + __expf(-(gxz.x + ghz.x)));
                        float zy = __fdividef(1.0f, 1.0f + __expf(-(gxz.y + ghz.y)));
                        float ax = fmaf(rx, ghn.x, gxn.x);
                        float ay = fmaf(ry, ghn.y, gxn.y);
                        float nx = 1.0f - __fdividef(2.0f, __expf(2.0f * ax) + 1.0f);
                        float ny = 1.0f - __fdividef(2.0f, __expf(2.0f * ay) + 1.0f);
                        float2 hn;
                        hn.x = live ? fmaf(zx, ho.x - nx, nx) : ho.x;
                        hn.y = live ? fmaf(zy, ho.y - ny, ny) : ho.y;
                        *reinterpret_cast<float2*>(hp) = hn;
                    }
                }
                __syncthreads();   // h published
                p ^= 1;
            }
        } else {
            __syncthreads();
        }

        // outputs: 512 float2 over 192 threads
        for (int u = j; u < WG * HS_DIM / 2; u += NT) {
            int s = u >> 5, ii = (u & 31) * 2;
            *reinterpret_cast<float2*>(&out[(long)seq_sm[s] * HS_DIM + ii]) =
                *reinterpret_cast<const float2*>(
                    reinterpret_cast<const float*>(h4[s]) + ii);
        }
        // next claim barrier orders smem reuse
    }
}

extern "C" void kernel_launch(void* const* d_in, const int* in_sizes, int n_in,
                              void* d_out, int out_size)
{
    const int*   x    = (const int*)  d_in[0];
    const float* emb  = (const float*)d_in[1];
    const float* w_ih = (const float*)d_in[2];
    const float* w_hh = (const float*)d_in[3];
    const float* b_ih = (const float*)d_in[4];
    const float* b_hh = (const float*)d_in[5];
    float*       out  = (float*)d_out;

    zero_kernel<<<1, 1024>>>();
    len_pre_kernel<<<LEN_CTAS + (VOCAB + P_ROWS_PER_CTA - 1) / P_ROWS_PER_CTA, 256>>>(
        x, emb, w_ih, b_ih);
    scan_scatter_kernel<<<1, 256>>>();
    gru_main<<<296, NT>>>(x, w_hh, b_hh, out);
}

// round 8
// speedup vs baseline: 1.1672x; 1.1672x over previous
#include <cuda_runtime.h>

// GRU sequence encoder, round 8 = R5 config + dual accumulators +
// vectorized epilogue + register-free prefetch.
// N=16384, L=512, ES=32, HS=64, gates [r|z|n] (torch order).
//
// P[v][g] = emb[v].w_ih[g] + b_ih[g] precomputed (32000x192, L2-resident).
// Counting sort by length (desc), 16 seqs per CTA group.
// 192-thread CTAs, thread j owns gate row j (64 weight regs -> ptxas has
// headroom to hoist/batch the L2 prefetch LDGs). Two FFMA2 chains per
// s-iteration so a warp can issue at full FMA-pipe density.

#define N_SEQ   16384
#define L_SEQ   512
#define ES_DIM  32
#define HS_DIM  64
#define G3      192
#define WG      16
#define NGROUP  (N_SEQ / WG)   // 1024
#define NBUCKET 513
#define VOCAB   32000
#define NT      192

__device__ float P[VOCAB * G3];
__device__ int d_len[N_SEQ];
__device__ int d_bucket[NBUCKET];
__device__ int d_off[NBUCKET];
__device__ int d_sorted[N_SEQ];
__device__ int g_ctr;

#define FFMA2(acc, a, b) \
    asm("fma.rn.f32x2 %0, %1, %2, %0;" : "+l"(acc) : "l"(a), "l"(b))

__device__ __forceinline__ float pairsum2(unsigned long long u,
                                          unsigned long long v) {
    // sum of all four packed floats in u, v
    float ux = __uint_as_float((unsigned)u);
    float uy = __uint_as_float((unsigned)(u >> 32));
    float vx = __uint_as_float((unsigned)v);
    float vy = __uint_as_float((unsigned)(v >> 32));
    return (ux + uy) + (vx + vy);
}

// ---------------- prepass ----------------

__global__ void zero_kernel() {
    int t = threadIdx.x;
    if (t < NBUCKET) d_bucket[t] = 0;
    if (t == NBUCKET) g_ctr = 0;
}

#define LEN_CTAS 2048
#define P_ROWS_PER_CTA 64

__global__ void len_pre_kernel(const int* __restrict__ x,
                               const float* __restrict__ emb,
                               const float* __restrict__ w_ih,
                               const float* __restrict__ b_ih)
{
    if (blockIdx.x < LEN_CTAS) {
        int seq  = blockIdx.x * 8 + (threadIdx.x >> 5);
        int lane = threadIdx.x & 31;
        const int4* row = reinterpret_cast<const int4*>(x + (long)seq * L_SEQ);
        int c = 0;
        #pragma unroll
        for (int k = 0; k < 4; k++) {
            int4 v = row[lane + 32 * k];
            c += (v.x != 0) + (v.y != 0) + (v.z != 0) + (v.w != 0);
        }
        #pragma unroll
        for (int off = 16; off > 0; off >>= 1) c += __shfl_xor_sync(~0u, c, off);
        if (lane == 0) {
            d_len[seq] = c;
            atomicAdd(&d_bucket[c], 1);
        }
    } else {
        int j = threadIdx.x;
        if (j >= G3) return;
        float w[ES_DIM];
        {
            const float4* wr = reinterpret_cast<const float4*>(w_ih + (long)j * ES_DIM);
            #pragma unroll
            for (int k = 0; k < ES_DIM / 4; k++) {
                float4 v = wr[k];
                w[4*k+0] = v.x; w[4*k+1] = v.y; w[4*k+2] = v.z; w[4*k+3] = v.w;
            }
        }
        const float bj = b_ih[j];
        int v0 = (blockIdx.x - LEN_CTAS) * P_ROWS_PER_CTA;
        for (int v = v0; v < v0 + P_ROWS_PER_CTA && v < VOCAB; v++) {
            const float4* er = reinterpret_cast<const float4*>(emb + (long)v * ES_DIM);
            float acc = bj;
            #pragma unroll
            for (int k = 0; k < ES_DIM / 4; k++) {
                float4 e = __ldg(&er[k]);
                acc = fmaf(w[4*k+0], e.x, acc);
                acc = fmaf(w[4*k+1], e.y, acc);
                acc = fmaf(w[4*k+2], e.z, acc);
                acc = fmaf(w[4*k+3], e.w, acc);
            }
            P[(long)v * G3 + j] = acc;
        }
    }
}

__global__ void scan_scatter_kernel() {
    __shared__ int sb[NBUCKET], so[NBUCKET];
    int t = threadIdx.x;
    for (int i = t; i < NBUCKET; i += blockDim.x) sb[i] = d_bucket[i];
    __syncthreads();
    if (t == 0) {
        int run = 0;
        for (int l = NBUCKET - 1; l >= 0; l--) { so[l] = run; run += sb[l]; }
    }
    __syncthreads();
    for (int i = t; i < NBUCKET; i += blockDim.x) d_off[i] = so[i];
    __syncthreads();
    for (int seq = t; seq < N_SEQ; seq += blockDim.x) {
        int l = d_len[seq];
        int pos = atomicAdd(&d_off[l], 1);
        d_sorted[pos] = seq;
    }
}

// ---------------- main ----------------

__launch_bounds__(NT, 2)
__global__ void gru_main(const int*   __restrict__ x,
                         const float* __restrict__ w_hh,
                         const float* __restrict__ b_hh,
                         float*       __restrict__ out)
{
    __shared__ float  gx[2][WG][G3];        // 24 KB (dbl-buffered P rows)
    __shared__ float  gate[3][WG][HS_DIM];  // 12 KB
    __shared__ float4 h4[WG][HS_DIM / 4];   //  4 KB
    __shared__ int    seq_sm[WG], len_sm[WG], gid_sm;

    const int j = threadIdx.x;              // gate row j
    const int i = j & 63;
    const int gsel = j >> 6;

    // one recurrent weight row in registers (64-bit packed pairs)
    ulonglong2 whh[HS_DIM / 4];
    {
        const ulonglong2* wp = reinterpret_cast<const ulonglong2*>(w_hh + (long)j * HS_DIM);
        #pragma unroll
        for (int k = 0; k < HS_DIM / 4; k++) whh[k] = wp[k];
    }
    const float bhh = b_hh[j];

    while (true) {
        if (j == 0) gid_sm = atomicAdd(&g_ctr, 1);
        __syncthreads();
        const int g = gid_sm;
        if (g >= NGROUP) break;

        if (j < WG) {
            int s = d_sorted[g * WG + j];
            seq_sm[j] = s;
            len_sm[j] = d_len[s];
        }
        for (int u = j; u < WG * (HS_DIM / 4); u += NT) {
            reinterpret_cast<float4*>(h4)[u] = make_float4(0.f, 0.f, 0.f, 0.f);
        }
        __syncthreads();

        const int maxlen = len_sm[0];
        int xoff[WG];
        #pragma unroll
        for (int s = 0; s < WG; s++) xoff[s] = seq_sm[s] * L_SEQ;

        if (maxlen > 0) {
            // prologue: gather gx(0) (scalar per thread per seq, coalesced)
            #pragma unroll
            for (int s = 0; s < WG; s++) {
                int tok = __ldg(&x[xoff[s]]);
                gx[0][s][j] = __ldg(&P[(long)tok * G3 + j]);
            }
            __syncthreads();

            int p = 0;
            for (int t = 0; t < maxlen; t++) {
                const int tn = (t + 1 < L_SEQ) ? t + 1 : L_SEQ - 1;

                // matvec (dual FFMA2 chains) + prefetch gx(t+1) -> idle buffer
                #pragma unroll
                for (int s = 0; s < WG; s++) {
                    int tok = __ldg(&x[xoff[s] + tn]);
                    float pre = __ldg(&P[(long)tok * G3 + j]);

                    unsigned long long a0 = 0ull, a1 = 0ull;
                    const ulonglong2* hp = reinterpret_cast<const ulonglong2*>(&h4[s][0]);
                    #pragma unroll
                    for (int k = 0; k < HS_DIM / 4; k++) {
                        ulonglong2 hv = hp[k];
                        FFMA2(a0, whh[k].x, hv.x);
                        FFMA2(a1, whh[k].y, hv.y);
                    }
                    gate[gsel][s][i] = pairsum2(a0, a1) + bhh;
                    gx[1 - p][s][j] = pre;
                }
                __syncthreads();   // gates + gx(t+1) ready; h reads done

                // update: 512 element-pairs over 192 threads (float2)
                #pragma unroll
                for (int q = 0; q < (WG * HS_DIM / 2 + NT - 1) / NT; q++) {
                    int u = j + NT * q;
                    if (u < WG * HS_DIM / 2) {
                        int s = u >> 5, ii = (u & 31) * 2;
                        float2 gxr = *reinterpret_cast<const float2*>(&gx[p][s][ii]);
                        float2 gxz = *reinterpret_cast<const float2*>(&gx[p][s][64 + ii]);
                        float2 gxn = *reinterpret_cast<const float2*>(&gx[p][s][128 + ii]);
                        float2 ghr = *reinterpret_cast<const float2*>(&gate[0][s][ii]);
                        float2 ghz = *reinterpret_cast<const float2*>(&gate[1][s][ii]);
                        float2 ghn = *reinterpret_cast<const float2*>(&gate[2][s][ii]);
                        float* hp = reinterpret_cast<float*>(h4[s]) + ii;
                        float2 ho = *reinterpret_cast<const float2*>(hp);
                        bool live = (t < len_sm[s]);

                        float rx = __fdividef(1.0f, 1.0f + __expf(-(gxr.x + ghr.x)));
                        float ry = __fdividef(1.0f, 1.0f + __expf(-(gxr.y + ghr.y)));
                        float zx = __fdividef(1.0f, 1.0f + __expf(-(gxz.x + ghz.x)));
                        float zy = __fdividef(1.0f, 1.0f + __expf(-(gxz.y + ghz.y)));
                        float ax = fmaf(rx, ghn.x, gxn.x);
                        float ay = fmaf(ry, ghn.y, gxn.y);
                        float nx = 1.0f - __fdividef(2.0f, __expf(2.0f * ax) + 1.0f);
                        float ny = 1.0f - __fdividef(2.0f, __expf(2.0f * ay) + 1.0f);
                        float2 hn;
                        hn.x = live ? fmaf(zx, ho.x - nx, nx) : ho.x;
                        hn.y = live ? fmaf(zy, ho.y - ny, ny) : ho.y;
                        *reinterpret_cast<float2*>(hp) = hn;
                    }
                }
                __syncthreads();   // h published
                p ^= 1;
            }
        } else {
            __syncthreads();
        }

        // outputs: 512 float2 over 192 threads
        for (int u = j; u < WG * HS_DIM / 2; u += NT) {
            int s = u >> 5, ii = (u & 31) * 2;
            *reinterpret_cast<float2*>(&out[(long)seq_sm[s] * HS_DIM + ii]) =
                *reinterpret_cast<const float2*>(
                    reinterpret_cast<const float*>(h4[s]) + ii);
        }
        // next claim barrier orders smem reuse
    }
}

extern "C" void kernel_launch(void* const* d_in, const int* in_sizes, int n_in,
                              void* d_out, int out_size)
{
    const int*   x    = (const int*)  d_in[0];
    const float* emb  = (const float*)d_in[1];
    const float* w_ih = (const float*)d_in[2];
    const float* w_hh = (const float*)d_in[3];
    const float* b_ih = (const float*)d_in[4];
    const float* b_hh = (const float*)d_in[5];
    float*       out  = (float*)d_out;

    zero_kernel<<<1, 1024>>>();
    len_pre_kernel<<<LEN_CTAS + (VOCAB + P_ROWS_PER_CTA - 1) / P_ROWS_PER_CTA, 256>>>(
        x, emb, w_ih, b_ih);
    scan_scatter_kernel<<<1, 256>>>();
    gru_main<<<296, NT>>>(x, w_hh, b_hh, out);
}